// round 14
// baseline (speedup 1.0000x reference)
#include <cuda_runtime.h>
#include <cuda_fp16.h>
#include <math.h>
#include <stdint.h>

// Problem constants (fixed by setup_inputs)
#define DIM   256
#define NHEAD 8
#define DHEAD 32
#define LQ    16320
#define PROJN 768
#define NQE   (LQ * DIM)

// Head-major value, two alignment copies (see deform v4).
#define HSZ_H (16324 * 32)
#define VHALF (8 * HSZ_H)

// fp16 weight buffer offsets (halfs)
#define WV_OFF   0
#define WSO_OFF  65536
#define WTSO_OFF 131072
#define WAW_OFF  196608
#define WTAW_OFF 229376
#define WO_OFF   262144
#define WTOT     327680

// Scratch (device globals)
__device__ __half g_value[16 * HSZ_H];
__device__ float  g_proj [LQ * PROJN];
__device__ __half g_mid  [LQ * DIM];
__device__ __half g_hq   [NQE];
__device__ __half g_hi   [NQE];
__device__ __half g_hw   [WTOT];

// ---------------- prep: fp32 -> fp16 one-pass convert ----------------
__device__ __forceinline__ uint32_t pack2(float a, float b) {
    __half2 h = __floats2half2_rn(a, b);
    return *(uint32_t*)&h;
}
__device__ __forceinline__ uint4 pack8(float4 v0, float4 v1) {
    uint4 u;
    u.x = pack2(v0.x, v0.y); u.y = pack2(v0.z, v0.w);
    u.z = pack2(v1.x, v1.y); u.w = pack2(v1.z, v1.w);
    return u;
}
__device__ __forceinline__ void cvt8(const float* s, __half* d) {
    float4 v0 = *(const float4*)(s);
    float4 v1 = *(const float4*)(s + 4);
    *(uint4*)d = pack8(v0, v1);
}

__global__ __launch_bounds__(256) void prep_kernel(
    const float* __restrict__ q, const float* __restrict__ inp,
    const float* __restrict__ wv, const float* __restrict__ wso,
    const float* __restrict__ wtso, const float* __restrict__ waw,
    const float* __restrict__ wtaw, const float* __restrict__ wo,
    __half* __restrict__ hq, __half* __restrict__ hi, __half* __restrict__ hw)
{
    int base = (blockIdx.x * 256 + threadIdx.x) * 8;
    if (base < NQE) {
        cvt8(q + base, hq + base);
    } else if (base < 2 * NQE) {
        int b = base - NQE;
        cvt8(inp + b, hi + b);
    } else {
        int b = base - 2 * NQE;
        if (b < WTOT) {
            const float* src; int off;
            if      (b < WSO_OFF)  { src = wv;   off = b; }
            else if (b < WTSO_OFF) { src = wso;  off = b - WSO_OFF; }
            else if (b < WAW_OFF)  { src = wtso; off = b - WTSO_OFF; }
            else if (b < WTAW_OFF) { src = waw;  off = b - WAW_OFF; }
            else if (b < WO_OFF)   { src = wtaw; off = b - WTAW_OFF; }
            else                   { src = wo;   off = b - WO_OFF; }
            cvt8(src + off, hw + b);
        }
    }
}

// ---------------- FP16 GEMM v6: cp.async 3-stage pipeline ----------------
// Templated row-tile NM (64 or 32). 256 threads = 8 warps (2x4),
// warp tile (NM/2)x32. All operands fp16; smem fill via cp.async.cg.
#define GBN 128
#define AROW 40
#define BROW 136
#define BBUFB (32 * BROW * 2)

struct Seg {
    const __half* A;
    const __half* B;
    const float*  bias;
    float*  Cf;
    __half* Ch;
    int ldb, boff, ldc, cn0, ishalf;
};
struct SegArr { Seg s[8]; };

__device__ __forceinline__ void cp16(uint32_t dst, const void* src) {
    asm volatile("cp.async.cg.shared.global [%0], [%1], 16;" :: "r"(dst), "l"(src));
}
__device__ __forceinline__ void ldsm4(uint32_t* r, uint32_t addr) {
    asm volatile("ldmatrix.sync.aligned.m8n8.x4.shared.b16 {%0,%1,%2,%3}, [%4];"
        : "=r"(r[0]), "=r"(r[1]), "=r"(r[2]), "=r"(r[3]) : "r"(addr));
}
__device__ __forceinline__ void ldsm4t(uint32_t* r, uint32_t addr) {
    asm volatile("ldmatrix.sync.aligned.m8n8.x4.trans.shared.b16 {%0,%1,%2,%3}, [%4];"
        : "=r"(r[0]), "=r"(r[1]), "=r"(r[2]), "=r"(r[3]) : "r"(addr));
}

template <int NM>
__global__ __launch_bounds__(256) void mma_gemm_v6(SegArr sa)
{
    constexpr int MI = NM / 32;            // m16 atoms per warp (2 or 1)
    constexpr int ABUFB = NM * AROW * 2;   // bytes/stage

    __shared__ __half As[3 * NM * AROW];
    __shared__ __half Bs[3 * 32 * BROW];

    const Seg sg = sa.s[blockIdx.x];
    const int tid = threadIdx.x;
    const int bm  = blockIdx.y * NM;

    const int lane = tid & 31, wid = tid >> 5;
    const int wm = wid >> 2, wn = wid & 3;
    const int g = lane >> 2, t = lane & 3;

    // A fill: row = tid>>2, col octet = (tid&3)*8. NM=64: all 256 threads
    // (rows 0..63). NM=32: threads 0..127 (rows 0..31).
    const int arow_f = tid >> 2;
    const int acol_f = (tid & 3) << 3;
    const bool a_on = (NM == 64) || (tid < 128);
    const __half* Agp = sg.A + (size_t)(bm + arow_f) * 256 + acol_f;
    const uint32_t as0 = (uint32_t)__cvta_generic_to_shared(As) +
                         ((arow_f * AROW + acol_f) << 1);

    const __half* Bgp0 = sg.B + (size_t)(tid >> 4) * sg.ldb + sg.boff + ((tid & 15) << 3);
    const __half* Bgp1 = Bgp0 + (size_t)16 * sg.ldb;
    const uint32_t bs0 = (uint32_t)__cvta_generic_to_shared(Bs) +
                         ((((tid >> 4) * BROW) + ((tid & 15) << 3)) << 1);
    const uint32_t bs1 = bs0 + 16 * BROW * 2;

    // ldmatrix lane addresses
    const uint32_t as_base = (uint32_t)__cvta_generic_to_shared(As);
    const uint32_t bs_base = (uint32_t)__cvta_generic_to_shared(Bs);
    const int arow = wm * (NM / 2) + (lane & 7) + ((lane >> 3) & 1) * 8;
    const int acol = (lane >> 4) * 8;
    const int brow = (lane & 7) + ((lane >> 3) & 1) * 8;
    const int bcol = wn * 32 + (lane >> 4) * 8;
    const uint32_t aaddr0 = as_base + (uint32_t)((arow * AROW + acol) * 2);
    const uint32_t baddr0 = bs_base + (uint32_t)((brow * BROW + bcol) * 2);

    float acc[MI][4][4] = {};

    #pragma unroll
    for (int s = 0; s < 2; ++s) {
        const int k0 = s * 32;
        if (a_on) cp16(as0 + s * ABUFB, Agp + k0);
        cp16(bs0 + s * BBUFB, Bgp0 + (size_t)k0 * sg.ldb);
        cp16(bs1 + s * BBUFB, Bgp1 + (size_t)k0 * sg.ldb);
        asm volatile("cp.async.commit_group;");
    }

    #pragma unroll
    for (int s = 0; s < 8; ++s) {
        if (s < 7) asm volatile("cp.async.wait_group 1;");
        else       asm volatile("cp.async.wait_group 0;");
        __syncthreads();

        if (s + 2 < 8) {
            const int st = (s + 2) % 3;
            const int k0 = (s + 2) * 32;
            if (a_on) cp16(as0 + st * ABUFB, Agp + k0);
            cp16(bs0 + st * BBUFB, Bgp0 + (size_t)k0 * sg.ldb);
            cp16(bs1 + st * BBUFB, Bgp1 + (size_t)k0 * sg.ldb);
            asm volatile("cp.async.commit_group;");
        }

        const int cur = s % 3;
        const uint32_t ab = aaddr0 + (uint32_t)(cur * ABUFB);
        const uint32_t bb = baddr0 + (uint32_t)(cur * BBUFB);
        #pragma unroll
        for (int ks = 0; ks < 2; ++ks) {
            uint32_t a[MI][4], b[2][4];
            #pragma unroll
            for (int mi = 0; mi < MI; ++mi)
                ldsm4(a[mi], ab + (uint32_t)((mi * 16 * AROW + ks * 16) * 2));
            #pragma unroll
            for (int nip = 0; nip < 2; ++nip)
                ldsm4t(b[nip], bb + (uint32_t)((ks * 16 * BROW + nip * 16) * 2));
            #pragma unroll
            for (int mi = 0; mi < MI; ++mi)
                #pragma unroll
                for (int ni = 0; ni < 4; ++ni) {
                    uint32_t b0 = b[ni >> 1][(ni & 1) * 2];
                    uint32_t b1 = b[ni >> 1][(ni & 1) * 2 + 1];
                    asm volatile(
                        "mma.sync.aligned.m16n8k16.row.col.f32.f16.f16.f32 "
                        "{%0,%1,%2,%3}, {%4,%5,%6,%7}, {%8,%9}, {%0,%1,%2,%3};"
                        : "+f"(acc[mi][ni][0]), "+f"(acc[mi][ni][1]),
                          "+f"(acc[mi][ni][2]), "+f"(acc[mi][ni][3])
                        : "r"(a[mi][0]), "r"(a[mi][1]), "r"(a[mi][2]), "r"(a[mi][3]),
                          "r"(b0), "r"(b1));
                }
        }
        if (s < 7) __syncthreads();
    }

    // ---- epilogue ----
    if (sg.ishalf) {
        const int head = (sg.cn0 >> 5) + wn;
        __half* baseA = sg.Ch + (size_t)head * HSZ_H;
        __half* baseB = sg.Ch + (size_t)VHALF + (size_t)head * HSZ_H;
        #pragma unroll
        for (int mi = 0; mi < MI; ++mi) {
            int row0 = bm + wm * (NM / 2) + mi * 16 + g;
            #pragma unroll
            for (int ni = 0; ni < 4; ++ni) {
                int ch = ni * 8 + t * 2;
                __half2 h0 = __floats2half2_rn(acc[mi][ni][0], acc[mi][ni][1]);
                __half2 h1 = __floats2half2_rn(acc[mi][ni][2], acc[mi][ni][3]);
                *(__half2*)(baseA + (size_t)(row0 + 1) * 32 + ch)  = h0;
                *(__half2*)(baseA + (size_t)(row0 + 9) * 32 + ch)  = h1;
                *(__half2*)(baseB + (size_t)(row0 + 2) * 32 + ch)  = h0;
                *(__half2*)(baseB + (size_t)(row0 + 10) * 32 + ch) = h1;
            }
        }
        if (blockIdx.x == 0 && blockIdx.y == 0) {
            int hh = tid >> 5, cc = tid & 31;
            sg.Ch[(size_t)hh * HSZ_H + cc] = __float2half(0.f);
            sg.Ch[(size_t)hh * HSZ_H + (size_t)16321 * 32 + cc] = __float2half(0.f);
        }
    } else {
        #pragma unroll
        for (int mi = 0; mi < MI; ++mi) {
            int row0 = bm + wm * (NM / 2) + mi * 16 + g;
            #pragma unroll
            for (int ni = 0; ni < 4; ++ni) {
                int lcol = wn * 32 + ni * 8 + t * 2;
                float2 bv2 = *(const float2*)(sg.bias + sg.boff + lcol);
                float v00 = acc[mi][ni][0] + bv2.x, v01 = acc[mi][ni][1] + bv2.y;
                float v10 = acc[mi][ni][2] + bv2.x, v11 = acc[mi][ni][3] + bv2.y;
                *(float2*)(sg.Cf + (size_t)row0 * sg.ldc + sg.cn0 + lcol)       = make_float2(v00, v01);
                *(float2*)(sg.Cf + (size_t)(row0 + 8) * sg.ldc + sg.cn0 + lcol) = make_float2(v10, v11);
            }
        }
    }
}

// ---------------- Deformable sampling + softmax v4.1 ----------------
__global__ __launch_bounds__(256) void deform_kernel(
    const float* __restrict__ proj,
    const __half* __restrict__ value,
    const float* __restrict__ refp,
    const float* __restrict__ toff,
    __half* __restrict__ mid)
{
    __shared__ float4 smw[256];
    __shared__ int2   smb[256];

    const int q    = blockIdx.x;
    const int warp = threadIdx.x >> 5;
    const int lane = threadIdx.x & 31;
    const int h = warp;
    const int l = lane >> 3;
    const int p = lane & 7;

    const int   Wl[4]  = {64, 32, 16, 8};
    const int   THl[4] = {192, 96, 48, 24};
    const int   STl[4] = {0, 12288, 15360, 16128};
    const int   Wv = Wl[l], TH = THl[l], start = STl[l];
    const float invW = 1.0f / (float)Wv, invTH = 1.0f / (float)TH;

    const float* prow = proj + (size_t)q * PROJN;

    int logit_col = (p < 4) ? (512 + h * 16 + l * 4 + p)
                            : (640 + h * 16 + l * 4 + (p - 4));
    float logit = prow[logit_col];
    float mx = logit;
    #pragma unroll
    for (int off = 16; off; off >>= 1) mx = fmaxf(mx, __shfl_xor_sync(0xffffffffu, mx, off));
    float e = __expf(logit - mx);
    float s = e;
    #pragma unroll
    for (int off = 16; off; off >>= 1) s += __shfl_xor_sync(0xffffffffu, s, off);
    float attnw = e / s;

    float rx = refp[q * 8 + l * 2 + 0];
    float ry = refp[q * 8 + l * 2 + 1];
    float ox, oy;
    if (p < 4) {
        int col = ((h * 4 + l) * 4 + p) * 2;
        ox = prow[col + 0] * invW;
        oy = prow[col + 1] * invTH;
    } else {
        int tw = (p - 4) >> 1, tp = (p - 4) & 1;
        int col = 256 + (((h * 4 + l) * 2 + tw) * 2 + tp) * 2;
        int tob = ((q * 4 + l) * 2 + tw) * 2;
        ox = toff[tob + 0] + prow[col + 0] * invW;
        oy = toff[tob + 1] + prow[col + 1] * invTH;
    }
    float x = (rx + ox) * (float)Wv - 0.5f;
    float y = (ry + oy) * (float)TH - 0.5f;

    float x0f = floorf(x), y0f = floorf(y);
    float lx = x - x0f, ly = y - y0f;
    int x0 = (int)x0f, y0 = (int)y0f;
    int x1 = x0 + 1,   y1 = y0 + 1;

    bool ix0 = (x0 >= 0) & (x0 < Wv);
    bool ix1 = (x1 >= 0) & (x1 < Wv);
    bool iy0 = (y0 >= 0) & (y0 < TH);
    bool iy1 = (y1 >= 0) & (y1 < TH);
    int cy0 = min(max(y0, 0), TH - 1);
    int cy1 = min(max(y1, 0), TH - 1);

    float4 w;
    w.x = attnw * (1.f - lx) * (1.f - ly) * (float)(ix0 & iy0);
    w.y = attnw * lx         * (1.f - ly) * (float)(ix1 & iy0);
    w.z = attnw * (1.f - lx) * ly         * (float)(ix0 & iy1);
    w.w = attnw * lx         * ly         * (float)(ix1 & iy1);

    int xb   = min(max(x0, -1), Wv - 1);
    int odd  = xb & 1;
    int shift = 1 + (odd ^ 1);
    int cbase = (odd ? 0 : VHALF) + h * HSZ_H;
    int pix0 = start + cy0 * Wv + xb;
    int pix1 = start + cy1 * Wv + xb;
    int2 bb;
    bb.x = cbase + (pix0 + shift) * 32;
    bb.y = cbase + (pix1 + shift) * 32;

    smw[threadIdx.x] = w;
    smb[threadIdx.x] = bb;
    __syncwarp();

    const int gg = lane >> 3;
    const int u  = lane & 7;
    const int xs = u >> 2;
    const int uoff = u << 3;

    // preload all 8 (weights, addrs) into registers to maximize LDG MLP
    float w0r[8], w1r[8];
    int   b0r[8], b1r[8];
    const int sbase = (warp << 5) + (gg << 3);
    #pragma unroll
    for (int pi = 0; pi < 8; ++pi) {
        float4 wv = smw[sbase + pi];
        int2  bp = smb[sbase + pi];
        w0r[pi] = xs ? wv.y : wv.x;
        w1r[pi] = xs ? wv.w : wv.z;
        b0r[pi] = bp.x + uoff;
        b1r[pi] = bp.y + uoff;
    }

    float acc[8] = {};
    #pragma unroll
    for (int pi = 0; pi < 8; ++pi) {
        uint4 v0 = __ldcg((const uint4*)(value + b0r[pi]));
        uint4 v1 = __ldcg((const uint4*)(value + b1r[pi]));
        float w0 = w0r[pi], w1 = w1r[pi];
        float2 a0 = __half22float2(*(__half2*)&v0.x);
        float2 a1 = __half22float2(*(__half2*)&v0.y);
        float2 a2 = __half22float2(*(__half2*)&v0.z);
        float2 a3 = __half22float2(*(__half2*)&v0.w);
        float2 c0 = __half22float2(*(__half2*)&v1.x);
        float2 c1 = __half22float2(*(__half2*)&v1.y);
        float2 c2 = __half22float2(*(__half2*)&v1.z);
        float2 c3 = __half22float2(*(__half2*)&v1.w);
        acc[0] += w0 * a0.x + w1 * c0.x; acc[1] += w0 * a0.y + w1 * c0.y;
        acc[2] += w0 * a1.x + w1 * c1.x; acc[3] += w0 * a1.y + w1 * c1.y;
        acc[4] += w0 * a2.x + w1 * c2.x; acc[5] += w0 * a2.y + w1 * c2.y;
        acc[6] += w0 * a3.x + w1 * c3.x; acc[7] += w0 * a3.y + w1 * c3.y;
    }
    #pragma unroll
    for (int j = 0; j < 8; ++j) {
        acc[j] += __shfl_xor_sync(0xffffffffu, acc[j], 4);
        acc[j] += __shfl_xor_sync(0xffffffffu, acc[j], 8);
        acc[j] += __shfl_xor_sync(0xffffffffu, acc[j], 16);
    }
    if (lane < 4) {
        uint4 o8;
        o8.x = pack2(acc[0], acc[1]);
        o8.y = pack2(acc[2], acc[3]);
        o8.z = pack2(acc[4], acc[5]);
        o8.w = pack2(acc[6], acc[7]);
        *(uint4*)(mid + (size_t)q * DIM + warp * DHEAD + (lane << 3)) = o8;
    }
}

__global__ void phase_pad_kernel() {}

// ---------------- launch ----------------
extern "C" void kernel_launch(void* const* d_in, const int* in_sizes, int n_in,
                              void* d_out, int out_size)
{
    const float* query = (const float*)d_in[0];
    const float* refp  = (const float*)d_in[1];
    const float* toff  = (const float*)d_in[2];
    const float* inpf  = (const float*)d_in[3];
    const float* W_so  = (const float*)d_in[6];
    const float* b_so  = (const float*)d_in[7];
    const float* W_tso = (const float*)d_in[8];
    const float* b_tso = (const float*)d_in[9];
    const float* W_aw  = (const float*)d_in[10];
    const float* b_aw  = (const float*)d_in[11];
    const float* W_taw = (const float*)d_in[12];
    const float* b_taw = (const float*)d_in[13];
    const float* W_v   = (const float*)d_in[14];
    const float* b_v   = (const float*)d_in[15];
    const float* W_o   = (const float*)d_in[16];
    const float* b_o   = (const float*)d_in[17];
    float* out = (float*)d_out;

    __half *value, *mid, *hq, *hi, *hw; float *proj;
    cudaGetSymbolAddress((void**)&value, g_value);
    cudaGetSymbolAddress((void**)&proj,  g_proj);
    cudaGetSymbolAddress((void**)&mid,   g_mid);
    cudaGetSymbolAddress((void**)&hq,    g_hq);
    cudaGetSymbolAddress((void**)&hi,    g_hi);
    cudaGetSymbolAddress((void**)&hw,    g_hw);

    dim3 blk(256);

    // (1) fp32 -> fp16 prep
    {
        int nthr = (2 * NQE + WTOT) / 8;
        prep_kernel<<<nthr / 256, 256>>>(query, inpf, W_v, W_so, W_tso, W_aw, W_taw, W_o,
                                         hq, hi, hw);
    }
    // (2) fused value + projections GEMM (8 segments, 64-row tiles)
    {
        SegArr sa{};
        for (int i = 0; i < 2; ++i) {
            sa.s[i].A = hi; sa.s[i].B = hw + WV_OFF; sa.s[i].bias = b_v;
            sa.s[i].Ch = value; sa.s[i].ldb = 256; sa.s[i].boff = i * 128;
            sa.s[i].ldc = DIM; sa.s[i].cn0 = i * 128; sa.s[i].ishalf = 1;
        }
        for (int i = 0; i < 2; ++i) {
            sa.s[2 + i].A = hq; sa.s[2 + i].B = hw + WSO_OFF; sa.s[2 + i].bias = b_so;
            sa.s[2 + i].Cf = proj; sa.s[2 + i].ldb = 256; sa.s[2 + i].boff = i * 128;
            sa.s[2 + i].ldc = PROJN; sa.s[2 + i].cn0 = i * 128; sa.s[2 + i].ishalf = 0;
            sa.s[4 + i].A = hq; sa.s[4 + i].B = hw + WTSO_OFF; sa.s[4 + i].bias = b_tso;
            sa.s[4 + i].Cf = proj; sa.s[4 + i].ldb = 256; sa.s[4 + i].boff = i * 128;
            sa.s[4 + i].ldc = PROJN; sa.s[4 + i].cn0 = 256 + i * 128; sa.s[4 + i].ishalf = 0;
        }
        sa.s[6].A = hq; sa.s[6].B = hw + WAW_OFF; sa.s[6].bias = b_aw;
        sa.s[6].Cf = proj; sa.s[6].ldb = 128; sa.s[6].boff = 0;
        sa.s[6].ldc = PROJN; sa.s[6].cn0 = 512; sa.s[6].ishalf = 0;
        sa.s[7].A = hq; sa.s[7].B = hw + WTAW_OFF; sa.s[7].bias = b_taw;
        sa.s[7].Cf = proj; sa.s[7].ldb = 128; sa.s[7].boff = 0;
        sa.s[7].ldc = PROJN; sa.s[7].cn0 = 640; sa.s[7].ishalf = 0;
        mma_gemm_v6<64><<<dim3(8, LQ / 64), blk>>>(sa);
    }
    // (3) pad: shifts deform to absolute launch #4 for ncu
    phase_pad_kernel<<<1, 32>>>();
    // (4) deform
    deform_kernel<<<LQ, 256>>>(proj, value, refp, toff, mid);
    // (5) out = mid @ W_o + b_o  (32-row tiles -> 1020 blocks)
    {
        SegArr sa{};
        for (int i = 0; i < 2; ++i) {
            sa.s[i].A = mid; sa.s[i].B = hw + WO_OFF; sa.s[i].bias = b_o;
            sa.s[i].Cf = out; sa.s[i].ldb = 256; sa.s[i].boff = i * 128;
            sa.s[i].ldc = DIM; sa.s[i].cn0 = i * 128; sa.s[i].ishalf = 0;
        }
        mma_gemm_v6<32><<<dim3(2, LQ / 32), blk>>>(sa);
    }
}

// round 15
// speedup vs baseline: 1.1408x; 1.1408x over previous
#include <cuda_runtime.h>
#include <cuda_fp16.h>
#include <math.h>
#include <stdint.h>

// Problem constants (fixed by setup_inputs)
#define DIM   256
#define NHEAD 8
#define DHEAD 32
#define LQ    16320
#define PROJN 768
#define NQE   (LQ * DIM)

// Head-major value, two alignment copies (see deform v4).
#define HSZ_H (16324 * 32)
#define VHALF (8 * HSZ_H)

// fp16 weight buffer offsets (halfs)
#define WV_OFF   0
#define WSO_OFF  65536
#define WTSO_OFF 131072
#define WAW_OFF  196608
#define WTAW_OFF 229376
#define WO_OFF   262144
#define WTOT     327680

// Scratch (device globals)
__device__ __half g_value[16 * HSZ_H];
__device__ float  g_proj [LQ * PROJN];
__device__ __half g_mid  [LQ * DIM];
__device__ __half g_hq   [NQE];
__device__ __half g_hi   [NQE];
__device__ __half g_hw   [WTOT];

// ---------------- prep: fp32 -> fp16 one-pass convert ----------------
__device__ __forceinline__ uint32_t pack2(float a, float b) {
    __half2 h = __floats2half2_rn(a, b);
    return *(uint32_t*)&h;
}
__device__ __forceinline__ uint4 pack8(float4 v0, float4 v1) {
    uint4 u;
    u.x = pack2(v0.x, v0.y); u.y = pack2(v0.z, v0.w);
    u.z = pack2(v1.x, v1.y); u.w = pack2(v1.z, v1.w);
    return u;
}
__device__ __forceinline__ void cvt8(const float* s, __half* d) {
    float4 v0 = *(const float4*)(s);
    float4 v1 = *(const float4*)(s + 4);
    *(uint4*)d = pack8(v0, v1);
}

__global__ __launch_bounds__(256) void prep_kernel(
    const float* __restrict__ q, const float* __restrict__ inp,
    const float* __restrict__ wv, const float* __restrict__ wso,
    const float* __restrict__ wtso, const float* __restrict__ waw,
    const float* __restrict__ wtaw, const float* __restrict__ wo,
    __half* __restrict__ hq, __half* __restrict__ hi, __half* __restrict__ hw)
{
    int base = (blockIdx.x * 256 + threadIdx.x) * 8;
    if (base < NQE) {
        cvt8(q + base, hq + base);
    } else if (base < 2 * NQE) {
        int b = base - NQE;
        cvt8(inp + b, hi + b);
    } else {
        int b = base - 2 * NQE;
        if (b < WTOT) {
            const float* src; int off;
            if      (b < WSO_OFF)  { src = wv;   off = b; }
            else if (b < WTSO_OFF) { src = wso;  off = b - WSO_OFF; }
            else if (b < WAW_OFF)  { src = wtso; off = b - WTSO_OFF; }
            else if (b < WTAW_OFF) { src = waw;  off = b - WAW_OFF; }
            else if (b < WO_OFF)   { src = wtaw; off = b - WTAW_OFF; }
            else                   { src = wo;   off = b - WO_OFF; }
            cvt8(src + off, hw + b);
        }
    }
}

// ---------------- FP16 GEMM v6: cp.async 3-stage pipeline ----------------
#define GBN 128
#define AROW 40
#define BROW 136
#define BBUFB (32 * BROW * 2)

struct Seg {
    const __half* A;
    const __half* B;
    const float*  bias;
    float*  Cf;
    __half* Ch;
    int ldb, boff, ldc, cn0, ishalf;
};
struct SegArr { Seg s[8]; };

__device__ __forceinline__ void cp16(uint32_t dst, const void* src) {
    asm volatile("cp.async.cg.shared.global [%0], [%1], 16;" :: "r"(dst), "l"(src));
}
__device__ __forceinline__ void ldsm4(uint32_t* r, uint32_t addr) {
    asm volatile("ldmatrix.sync.aligned.m8n8.x4.shared.b16 {%0,%1,%2,%3}, [%4];"
        : "=r"(r[0]), "=r"(r[1]), "=r"(r[2]), "=r"(r[3]) : "r"(addr));
}
__device__ __forceinline__ void ldsm4t(uint32_t* r, uint32_t addr) {
    asm volatile("ldmatrix.sync.aligned.m8n8.x4.trans.shared.b16 {%0,%1,%2,%3}, [%4];"
        : "=r"(r[0]), "=r"(r[1]), "=r"(r[2]), "=r"(r[3]) : "r"(addr));
}

template <int NM>
__global__ __launch_bounds__(256) void mma_gemm_v6(SegArr sa)
{
    constexpr int MI = NM / 32;
    constexpr int ABUFB = NM * AROW * 2;

    __shared__ __half As[3 * NM * AROW];
    __shared__ __half Bs[3 * 32 * BROW];

    const Seg sg = sa.s[blockIdx.x];
    const int tid = threadIdx.x;
    const int bm  = blockIdx.y * NM;

    const int lane = tid & 31, wid = tid >> 5;
    const int wm = wid >> 2, wn = wid & 3;
    const int g = lane >> 2, t = lane & 3;

    const int arow_f = tid >> 2;
    const int acol_f = (tid & 3) << 3;
    const bool a_on = (NM == 64) || (tid < 128);
    const __half* Agp = sg.A + (size_t)(bm + arow_f) * 256 + acol_f;
    const uint32_t as0 = (uint32_t)__cvta_generic_to_shared(As) +
                         ((arow_f * AROW + acol_f) << 1);

    const __half* Bgp0 = sg.B + (size_t)(tid >> 4) * sg.ldb + sg.boff + ((tid & 15) << 3);
    const __half* Bgp1 = Bgp0 + (size_t)16 * sg.ldb;
    const uint32_t bs0 = (uint32_t)__cvta_generic_to_shared(Bs) +
                         ((((tid >> 4) * BROW) + ((tid & 15) << 3)) << 1);
    const uint32_t bs1 = bs0 + 16 * BROW * 2;

    const uint32_t as_base = (uint32_t)__cvta_generic_to_shared(As);
    const uint32_t bs_base = (uint32_t)__cvta_generic_to_shared(Bs);
    const int arow = wm * (NM / 2) + (lane & 7) + ((lane >> 3) & 1) * 8;
    const int acol = (lane >> 4) * 8;
    const int brow = (lane & 7) + ((lane >> 3) & 1) * 8;
    const int bcol = wn * 32 + (lane >> 4) * 8;
    const uint32_t aaddr0 = as_base + (uint32_t)((arow * AROW + acol) * 2);
    const uint32_t baddr0 = bs_base + (uint32_t)((brow * BROW + bcol) * 2);

    float acc[MI][4][4] = {};

    #pragma unroll
    for (int s = 0; s < 2; ++s) {
        const int k0 = s * 32;
        if (a_on) cp16(as0 + s * ABUFB, Agp + k0);
        cp16(bs0 + s * BBUFB, Bgp0 + (size_t)k0 * sg.ldb);
        cp16(bs1 + s * BBUFB, Bgp1 + (size_t)k0 * sg.ldb);
        asm volatile("cp.async.commit_group;");
    }

    #pragma unroll
    for (int s = 0; s < 8; ++s) {
        if (s < 7) asm volatile("cp.async.wait_group 1;");
        else       asm volatile("cp.async.wait_group 0;");
        __syncthreads();

        if (s + 2 < 8) {
            const int st = (s + 2) % 3;
            const int k0 = (s + 2) * 32;
            if (a_on) cp16(as0 + st * ABUFB, Agp + k0);
            cp16(bs0 + st * BBUFB, Bgp0 + (size_t)k0 * sg.ldb);
            cp16(bs1 + st * BBUFB, Bgp1 + (size_t)k0 * sg.ldb);
            asm volatile("cp.async.commit_group;");
        }

        const int cur = s % 3;
        const uint32_t ab = aaddr0 + (uint32_t)(cur * ABUFB);
        const uint32_t bb = baddr0 + (uint32_t)(cur * BBUFB);
        #pragma unroll
        for (int ks = 0; ks < 2; ++ks) {
            uint32_t a[MI][4], b[2][4];
            #pragma unroll
            for (int mi = 0; mi < MI; ++mi)
                ldsm4(a[mi], ab + (uint32_t)((mi * 16 * AROW + ks * 16) * 2));
            #pragma unroll
            for (int nip = 0; nip < 2; ++nip)
                ldsm4t(b[nip], bb + (uint32_t)((ks * 16 * BROW + nip * 16) * 2));
            #pragma unroll
            for (int mi = 0; mi < MI; ++mi)
                #pragma unroll
                for (int ni = 0; ni < 4; ++ni) {
                    uint32_t b0 = b[ni >> 1][(ni & 1) * 2];
                    uint32_t b1 = b[ni >> 1][(ni & 1) * 2 + 1];
                    asm volatile(
                        "mma.sync.aligned.m16n8k16.row.col.f32.f16.f16.f32 "
                        "{%0,%1,%2,%3}, {%4,%5,%6,%7}, {%8,%9}, {%0,%1,%2,%3};"
                        : "+f"(acc[mi][ni][0]), "+f"(acc[mi][ni][1]),
                          "+f"(acc[mi][ni][2]), "+f"(acc[mi][ni][3])
                        : "r"(a[mi][0]), "r"(a[mi][1]), "r"(a[mi][2]), "r"(a[mi][3]),
                          "r"(b0), "r"(b1));
                }
        }
        if (s < 7) __syncthreads();
    }

    // ---- epilogue ----
    if (sg.ishalf) {
        const int head = (sg.cn0 >> 5) + wn;
        __half* baseA = sg.Ch + (size_t)head * HSZ_H;
        __half* baseB = sg.Ch + (size_t)VHALF + (size_t)head * HSZ_H;
        #pragma unroll
        for (int mi = 0; mi < MI; ++mi) {
            int row0 = bm + wm * (NM / 2) + mi * 16 + g;
            #pragma unroll
            for (int ni = 0; ni < 4; ++ni) {
                int ch = ni * 8 + t * 2;
                __half2 h0 = __floats2half2_rn(acc[mi][ni][0], acc[mi][ni][1]);
                __half2 h1 = __floats2half2_rn(acc[mi][ni][2], acc[mi][ni][3]);
                *(__half2*)(baseA + (size_t)(row0 + 1) * 32 + ch)  = h0;
                *(__half2*)(baseA + (size_t)(row0 + 9) * 32 + ch)  = h1;
                *(__half2*)(baseB + (size_t)(row0 + 2) * 32 + ch)  = h0;
                *(__half2*)(baseB + (size_t)(row0 + 10) * 32 + ch) = h1;
            }
        }
        if (blockIdx.x == 0 && blockIdx.y == 0) {
            int hh = tid >> 5, cc = tid & 31;
            sg.Ch[(size_t)hh * HSZ_H + cc] = __float2half(0.f);
            sg.Ch[(size_t)hh * HSZ_H + (size_t)16321 * 32 + cc] = __float2half(0.f);
        }
    } else {
        #pragma unroll
        for (int mi = 0; mi < MI; ++mi) {
            int row0 = bm + wm * (NM / 2) + mi * 16 + g;
            #pragma unroll
            for (int ni = 0; ni < 4; ++ni) {
                int lcol = wn * 32 + ni * 8 + t * 2;
                float2 bv2 = *(const float2*)(sg.bias + sg.boff + lcol);
                float v00 = acc[mi][ni][0] + bv2.x, v01 = acc[mi][ni][1] + bv2.y;
                float v10 = acc[mi][ni][2] + bv2.x, v11 = acc[mi][ni][3] + bv2.y;
                *(float2*)(sg.Cf + (size_t)row0 * sg.ldc + sg.cn0 + lcol)       = make_float2(v00, v01);
                *(float2*)(sg.Cf + (size_t)(row0 + 8) * sg.ldc + sg.cn0 + lcol) = make_float2(v10, v11);
            }
        }
    }
}

// ---------------- Deformable sampling + softmax v5 ----------------
// Issue-count-optimized accumulation: HFMA2 in half2, flushed to fp32
// every 4 iterations (fp16 rounding depth <= 8 on lane-local partials).
__global__ __launch_bounds__(256) void deform_kernel(
    const float* __restrict__ proj,
    const __half* __restrict__ value,
    const float* __restrict__ refp,
    const float* __restrict__ toff,
    __half* __restrict__ mid)
{
    __shared__ float4 smw[256];
    __shared__ int2   smb[256];

    const int q    = blockIdx.x;
    const int warp = threadIdx.x >> 5;
    const int lane = threadIdx.x & 31;
    const int h = warp;
    const int l = lane >> 3;
    const int p = lane & 7;

    const int   Wv = 64 >> l;
    const int   TH = 192 >> l;
    const int   start = 16384 - (16384 >> (2 * l));
    const float invW  = __uint_as_float((uint32_t)(121 + l) << 23);      // exact 1/(64>>l)
    const float invTH = invW * 0.3333333333333333f;                      // 1/(192>>l)

    const float* prow = proj + (size_t)q * PROJN;

    int logit_col = (p < 4) ? (512 + h * 16 + l * 4 + p)
                            : (640 + h * 16 + l * 4 + (p - 4));
    float logit = prow[logit_col];
    float mx = logit;
    #pragma unroll
    for (int off = 16; off; off >>= 1) mx = fmaxf(mx, __shfl_xor_sync(0xffffffffu, mx, off));
    float e = __expf(logit - mx);
    float s = e;
    #pragma unroll
    for (int off = 16; off; off >>= 1) s += __shfl_xor_sync(0xffffffffu, s, off);
    float attnw = e / s;

    float rx = refp[q * 8 + l * 2 + 0];
    float ry = refp[q * 8 + l * 2 + 1];
    float ox, oy;
    if (p < 4) {
        int col = ((h * 4 + l) * 4 + p) * 2;
        ox = prow[col + 0] * invW;
        oy = prow[col + 1] * invTH;
    } else {
        int tw = (p - 4) >> 1, tp = (p - 4) & 1;
        int col = 256 + (((h * 4 + l) * 2 + tw) * 2 + tp) * 2;
        int tob = ((q * 4 + l) * 2 + tw) * 2;
        ox = toff[tob + 0] + prow[col + 0] * invW;
        oy = toff[tob + 1] + prow[col + 1] * invTH;
    }
    float x = (rx + ox) * (float)Wv - 0.5f;
    float y = (ry + oy) * (float)TH - 0.5f;

    float x0f = floorf(x), y0f = floorf(y);
    float lx = x - x0f, ly = y - y0f;
    int x0 = (int)x0f, y0 = (int)y0f;
    int x1 = x0 + 1,   y1 = y0 + 1;

    bool ix0 = (x0 >= 0) & (x0 < Wv);
    bool ix1 = (x1 >= 0) & (x1 < Wv);
    bool iy0 = (y0 >= 0) & (y0 < TH);
    bool iy1 = (y1 >= 0) & (y1 < TH);
    int cy0 = min(max(y0, 0), TH - 1);
    int cy1 = min(max(y1, 0), TH - 1);

    float4 w;
    w.x = attnw * (1.f - lx) * (1.f - ly) * (float)(ix0 & iy0);
    w.y = attnw * lx         * (1.f - ly) * (float)(ix1 & iy0);
    w.z = attnw * (1.f - lx) * ly         * (float)(ix0 & iy1);
    w.w = attnw * lx         * ly         * (float)(ix1 & iy1);

    int xb   = min(max(x0, -1), Wv - 1);
    int odd  = xb & 1;
    int shift = 1 + (odd ^ 1);
    int cbase = (odd ? 0 : VHALF) + h * HSZ_H;
    int pix0 = start + cy0 * Wv + xb;
    int pix1 = start + cy1 * Wv + xb;
    int2 bb;
    bb.x = cbase + (pix0 + shift) * 32;
    bb.y = cbase + (pix1 + shift) * 32;

    smw[threadIdx.x] = w;
    smb[threadIdx.x] = bb;
    __syncwarp();

    const int gg = lane >> 3;
    const int u  = lane & 7;
    const int xs = u >> 2;
    const int uoff = u << 3;
    const int sbase = (warp << 5) + (gg << 3);

    float accf[8] = {};
    #pragma unroll
    for (int seg = 0; seg < 2; ++seg) {
        __half2 acch[4];
        #pragma unroll
        for (int j = 0; j < 4; ++j) acch[j] = __half2half2(__float2half(0.f));
        #pragma unroll
        for (int pi4 = 0; pi4 < 4; ++pi4) {
            int pi = seg * 4 + pi4;
            float4 wv = smw[sbase + pi];
            int2  bp = smb[sbase + pi];
            float w0 = xs ? wv.y : wv.x;
            float w1 = xs ? wv.w : wv.z;
            __half2 w0h = __float2half2_rn(w0);
            __half2 w1h = __float2half2_rn(w1);
            uint4 v0 = __ldcg((const uint4*)(value + bp.x + uoff));
            uint4 v1 = __ldcg((const uint4*)(value + bp.y + uoff));
            const __half2* p0 = (const __half2*)&v0;
            const __half2* p1 = (const __half2*)&v1;
            #pragma unroll
            for (int j = 0; j < 4; ++j) {
                acch[j] = __hfma2(p0[j], w0h, acch[j]);
                acch[j] = __hfma2(p1[j], w1h, acch[j]);
            }
        }
        #pragma unroll
        for (int j = 0; j < 4; ++j) {
            float2 f = __half22float2(acch[j]);
            accf[2 * j]     += f.x;
            accf[2 * j + 1] += f.y;
        }
    }
    #pragma unroll
    for (int j = 0; j < 8; ++j) {
        accf[j] += __shfl_xor_sync(0xffffffffu, accf[j], 4);
        accf[j] += __shfl_xor_sync(0xffffffffu, accf[j], 8);
        accf[j] += __shfl_xor_sync(0xffffffffu, accf[j], 16);
    }
    if (lane < 4) {
        uint4 o8;
        o8.x = pack2(accf[0], accf[1]);
        o8.y = pack2(accf[2], accf[3]);
        o8.z = pack2(accf[4], accf[5]);
        o8.w = pack2(accf[6], accf[7]);
        *(uint4*)(mid + (size_t)q * DIM + warp * DHEAD + (lane << 3)) = o8;
    }
}

// ---------------- launch ----------------
extern "C" void kernel_launch(void* const* d_in, const int* in_sizes, int n_in,
                              void* d_out, int out_size)
{
    const float* query = (const float*)d_in[0];
    const float* refp  = (const float*)d_in[1];
    const float* toff  = (const float*)d_in[2];
    const float* inpf  = (const float*)d_in[3];
    const float* W_so  = (const float*)d_in[6];
    const float* b_so  = (const float*)d_in[7];
    const float* W_tso = (const float*)d_in[8];
    const float* b_tso = (const float*)d_in[9];
    const float* W_aw  = (const float*)d_in[10];
    const float* b_aw  = (const float*)d_in[11];
    const float* W_taw = (const float*)d_in[12];
    const float* b_taw = (const float*)d_in[13];
    const float* W_v   = (const float*)d_in[14];
    const float* b_v   = (const float*)d_in[15];
    const float* W_o   = (const float*)d_in[16];
    const float* b_o   = (const float*)d_in[17];
    float* out = (float*)d_out;

    __half *value, *mid, *hq, *hi, *hw; float *proj;
    cudaGetSymbolAddress((void**)&value, g_value);
    cudaGetSymbolAddress((void**)&proj,  g_proj);
    cudaGetSymbolAddress((void**)&mid,   g_mid);
    cudaGetSymbolAddress((void**)&hq,    g_hq);
    cudaGetSymbolAddress((void**)&hi,    g_hi);
    cudaGetSymbolAddress((void**)&hw,    g_hw);

    dim3 blk(256);

    // (1) fp32 -> fp16 prep
    {
        int nthr = (2 * NQE + WTOT) / 8;
        prep_kernel<<<nthr / 256, 256>>>(query, inpf, W_v, W_so, W_tso, W_aw, W_taw, W_o,
                                         hq, hi, hw);
    }
    // (2) fused value + projections GEMM (8 segments, 64-row tiles)
    {
        SegArr sa{};
        for (int i = 0; i < 2; ++i) {
            sa.s[i].A = hi; sa.s[i].B = hw + WV_OFF; sa.s[i].bias = b_v;
            sa.s[i].Ch = value; sa.s[i].ldb = 256; sa.s[i].boff = i * 128;
            sa.s[i].ldc = DIM; sa.s[i].cn0 = i * 128; sa.s[i].ishalf = 1;
        }
        for (int i = 0; i < 2; ++i) {
            sa.s[2 + i].A = hq; sa.s[2 + i].B = hw + WSO_OFF; sa.s[2 + i].bias = b_so;
            sa.s[2 + i].Cf = proj; sa.s[2 + i].ldb = 256; sa.s[2 + i].boff = i * 128;
            sa.s[2 + i].ldc = PROJN; sa.s[2 + i].cn0 = i * 128; sa.s[2 + i].ishalf = 0;
            sa.s[4 + i].A = hq; sa.s[4 + i].B = hw + WTSO_OFF; sa.s[4 + i].bias = b_tso;
            sa.s[4 + i].Cf = proj; sa.s[4 + i].ldb = 256; sa.s[4 + i].boff = i * 128;
            sa.s[4 + i].ldc = PROJN; sa.s[4 + i].cn0 = 256 + i * 128; sa.s[4 + i].ishalf = 0;
        }
        sa.s[6].A = hq; sa.s[6].B = hw + WAW_OFF; sa.s[6].bias = b_aw;
        sa.s[6].Cf = proj; sa.s[6].ldb = 128; sa.s[6].boff = 0;
        sa.s[6].ldc = PROJN; sa.s[6].cn0 = 512; sa.s[6].ishalf = 0;
        sa.s[7].A = hq; sa.s[7].B = hw + WTAW_OFF; sa.s[7].bias = b_taw;
        sa.s[7].Cf = proj; sa.s[7].ldb = 128; sa.s[7].boff = 0;
        sa.s[7].ldc = PROJN; sa.s[7].cn0 = 640; sa.s[7].ishalf = 0;
        mma_gemm_v6<64><<<dim3(8, LQ / 64), blk>>>(sa);
    }
    // (3) deform
    deform_kernel<<<LQ, 256>>>(proj, value, refp, toff, mid);
    // (4) out = mid @ W_o + b_o  (32-row tiles -> 1020 blocks)
    {
        SegArr sa{};
        for (int i = 0; i < 2; ++i) {
            sa.s[i].A = mid; sa.s[i].B = hw + WO_OFF; sa.s[i].bias = b_o;
            sa.s[i].Cf = out; sa.s[i].ldb = 256; sa.s[i].boff = i * 128;
            sa.s[i].ldc = DIM; sa.s[i].cn0 = i * 128; sa.s[i].ishalf = 0;
        }
        mma_gemm_v6<32><<<dim3(2, LQ / 32), blk>>>(sa);
    }
}

// round 16
// speedup vs baseline: 1.1573x; 1.0145x over previous
#include <cuda_runtime.h>
#include <cuda_fp16.h>
#include <math.h>
#include <stdint.h>

// Problem constants (fixed by setup_inputs)
#define DIM   256
#define NHEAD 8
#define DHEAD 32
#define LQ    16320
#define PROJN 768
#define NQE   (LQ * DIM)

// Head-major value, two alignment copies (see deform v4).
#define HSZ_H (16324 * 32)
#define VHALF (8 * HSZ_H)

// fp16 weight buffer offsets (halfs)
#define WV_OFF   0
#define WSO_OFF  65536
#define WTSO_OFF 131072
#define WAW_OFF  196608
#define WTAW_OFF 229376
#define WO_OFF   262144
#define WTOT     327680

// Scratch (device globals)
__device__ __half g_value[16 * HSZ_H];
__device__ float  g_proj [LQ * PROJN];
__device__ __half g_mid  [LQ * DIM];
__device__ __half g_hq   [NQE];
__device__ __half g_hi   [NQE];
__device__ __half g_hw   [WTOT];

// ---------------- prep: fp32 -> fp16 one-pass convert ----------------
__device__ __forceinline__ uint32_t pack2(float a, float b) {
    __half2 h = __floats2half2_rn(a, b);
    return *(uint32_t*)&h;
}
__device__ __forceinline__ uint4 pack8(float4 v0, float4 v1) {
    uint4 u;
    u.x = pack2(v0.x, v0.y); u.y = pack2(v0.z, v0.w);
    u.z = pack2(v1.x, v1.y); u.w = pack2(v1.z, v1.w);
    return u;
}
__device__ __forceinline__ void cvt8(const float* s, __half* d) {
    float4 v0 = *(const float4*)(s);
    float4 v1 = *(const float4*)(s + 4);
    *(uint4*)d = pack8(v0, v1);
}

__global__ __launch_bounds__(256) void prep_kernel(
    const float* __restrict__ q, const float* __restrict__ inp,
    const float* __restrict__ wv, const float* __restrict__ wso,
    const float* __restrict__ wtso, const float* __restrict__ waw,
    const float* __restrict__ wtaw, const float* __restrict__ wo,
    __half* __restrict__ hq, __half* __restrict__ hi, __half* __restrict__ hw)
{
    int base = (blockIdx.x * 256 + threadIdx.x) * 8;
    if (base < NQE) {
        cvt8(q + base, hq + base);
    } else if (base < 2 * NQE) {
        int b = base - NQE;
        cvt8(inp + b, hi + b);
    } else {
        int b = base - 2 * NQE;
        if (b < WTOT) {
            const float* src; int off;
            if      (b < WSO_OFF)  { src = wv;   off = b; }
            else if (b < WTSO_OFF) { src = wso;  off = b - WSO_OFF; }
            else if (b < WAW_OFF)  { src = wtso; off = b - WTSO_OFF; }
            else if (b < WTAW_OFF) { src = waw;  off = b - WAW_OFF; }
            else if (b < WO_OFF)   { src = wtaw; off = b - WTAW_OFF; }
            else                   { src = wo;   off = b - WO_OFF; }
            cvt8(src + off, hw + b);
        }
    }
}

// ---------------- FP16 GEMM v6: cp.async 3-stage pipeline (NM=64) ---------
#define GBN 128
#define AROW 40
#define BROW 136
#define BBUFB (32 * BROW * 2)
#define ABUFB (64 * AROW * 2)

struct Seg {
    const __half* A;
    const __half* B;
    const float*  bias;
    float*  Cf;
    __half* Ch;
    int ldb, boff, ldc, cn0, ishalf;
};
struct SegArr { Seg s[8]; };

__device__ __forceinline__ void cp16(uint32_t dst, const void* src) {
    asm volatile("cp.async.cg.shared.global [%0], [%1], 16;" :: "r"(dst), "l"(src));
}
__device__ __forceinline__ void ldsm4(uint32_t* r, uint32_t addr) {
    asm volatile("ldmatrix.sync.aligned.m8n8.x4.shared.b16 {%0,%1,%2,%3}, [%4];"
        : "=r"(r[0]), "=r"(r[1]), "=r"(r[2]), "=r"(r[3]) : "r"(addr));
}
__device__ __forceinline__ void ldsm4t(uint32_t* r, uint32_t addr) {
    asm volatile("ldmatrix.sync.aligned.m8n8.x4.trans.shared.b16 {%0,%1,%2,%3}, [%4];"
        : "=r"(r[0]), "=r"(r[1]), "=r"(r[2]), "=r"(r[3]) : "r"(addr));
}

__global__ __launch_bounds__(256) void mma_gemm_v6(SegArr sa)
{
    __shared__ __half As[3 * 64 * AROW];
    __shared__ __half Bs[3 * 32 * BROW];

    const Seg sg = sa.s[blockIdx.x];
    const int tid = threadIdx.x;
    const int bm  = blockIdx.y * 64;

    const int lane = tid & 31, wid = tid >> 5;
    const int wm = wid >> 2, wn = wid & 3;
    const int g = lane >> 2, t = lane & 3;

    const int arow_f = tid >> 2;
    const int acol_f = (tid & 3) << 3;
    const __half* Agp = sg.A + (size_t)(bm + arow_f) * 256 + acol_f;
    const uint32_t as0 = (uint32_t)__cvta_generic_to_shared(As) +
                         ((arow_f * AROW + acol_f) << 1);

    const __half* Bgp0 = sg.B + (size_t)(tid >> 4) * sg.ldb + sg.boff + ((tid & 15) << 3);
    const __half* Bgp1 = Bgp0 + (size_t)16 * sg.ldb;
    const uint32_t bs0 = (uint32_t)__cvta_generic_to_shared(Bs) +
                         ((((tid >> 4) * BROW) + ((tid & 15) << 3)) << 1);
    const uint32_t bs1 = bs0 + 16 * BROW * 2;

    const uint32_t as_base = (uint32_t)__cvta_generic_to_shared(As);
    const uint32_t bs_base = (uint32_t)__cvta_generic_to_shared(Bs);
    const int arow = wm * 32 + (lane & 7) + ((lane >> 3) & 1) * 8;
    const int acol = (lane >> 4) * 8;
    const int brow = (lane & 7) + ((lane >> 3) & 1) * 8;
    const int bcol = wn * 32 + (lane >> 4) * 8;
    const uint32_t aaddr0 = as_base + (uint32_t)((arow * AROW + acol) * 2);
    const uint32_t baddr0 = bs_base + (uint32_t)((brow * BROW + bcol) * 2);

    float acc[2][4][4] = {};

    #pragma unroll
    for (int s = 0; s < 2; ++s) {
        const int k0 = s * 32;
        cp16(as0 + s * ABUFB, Agp + k0);
        cp16(bs0 + s * BBUFB, Bgp0 + (size_t)k0 * sg.ldb);
        cp16(bs1 + s * BBUFB, Bgp1 + (size_t)k0 * sg.ldb);
        asm volatile("cp.async.commit_group;");
    }

    #pragma unroll
    for (int s = 0; s < 8; ++s) {
        if (s < 7) asm volatile("cp.async.wait_group 1;");
        else       asm volatile("cp.async.wait_group 0;");
        __syncthreads();

        if (s + 2 < 8) {
            const int st = (s + 2) % 3;
            const int k0 = (s + 2) * 32;
            cp16(as0 + st * ABUFB, Agp + k0);
            cp16(bs0 + st * BBUFB, Bgp0 + (size_t)k0 * sg.ldb);
            cp16(bs1 + st * BBUFB, Bgp1 + (size_t)k0 * sg.ldb);
            asm volatile("cp.async.commit_group;");
        }

        const int cur = s % 3;
        const uint32_t ab = aaddr0 + (uint32_t)(cur * ABUFB);
        const uint32_t bb = baddr0 + (uint32_t)(cur * BBUFB);
        #pragma unroll
        for (int ks = 0; ks < 2; ++ks) {
            uint32_t a[2][4], b[2][4];
            #pragma unroll
            for (int mi = 0; mi < 2; ++mi)
                ldsm4(a[mi], ab + (uint32_t)((mi * 16 * AROW + ks * 16) * 2));
            #pragma unroll
            for (int nip = 0; nip < 2; ++nip)
                ldsm4t(b[nip], bb + (uint32_t)((ks * 16 * BROW + nip * 16) * 2));
            #pragma unroll
            for (int mi = 0; mi < 2; ++mi)
                #pragma unroll
                for (int ni = 0; ni < 4; ++ni) {
                    uint32_t b0 = b[ni >> 1][(ni & 1) * 2];
                    uint32_t b1 = b[ni >> 1][(ni & 1) * 2 + 1];
                    asm volatile(
                        "mma.sync.aligned.m16n8k16.row.col.f32.f16.f16.f32 "
                        "{%0,%1,%2,%3}, {%4,%5,%6,%7}, {%8,%9}, {%0,%1,%2,%3};"
                        : "+f"(acc[mi][ni][0]), "+f"(acc[mi][ni][1]),
                          "+f"(acc[mi][ni][2]), "+f"(acc[mi][ni][3])
                        : "r"(a[mi][0]), "r"(a[mi][1]), "r"(a[mi][2]), "r"(a[mi][3]),
                          "r"(b0), "r"(b1));
                }
        }
        if (s < 7) __syncthreads();
    }

    // ---- epilogue ----
    if (sg.ishalf) {
        const int head = (sg.cn0 >> 5) + wn;
        __half* baseA = sg.Ch + (size_t)head * HSZ_H;
        __half* baseB = sg.Ch + (size_t)VHALF + (size_t)head * HSZ_H;
        #pragma unroll
        for (int mi = 0; mi < 2; ++mi) {
            int row0 = bm + wm * 32 + mi * 16 + g;
            #pragma unroll
            for (int ni = 0; ni < 4; ++ni) {
                int ch = ni * 8 + t * 2;
                __half2 h0 = __floats2half2_rn(acc[mi][ni][0], acc[mi][ni][1]);
                __half2 h1 = __floats2half2_rn(acc[mi][ni][2], acc[mi][ni][3]);
                *(__half2*)(baseA + (size_t)(row0 + 1) * 32 + ch)  = h0;
                *(__half2*)(baseA + (size_t)(row0 + 9) * 32 + ch)  = h1;
                *(__half2*)(baseB + (size_t)(row0 + 2) * 32 + ch)  = h0;
                *(__half2*)(baseB + (size_t)(row0 + 10) * 32 + ch) = h1;
            }
        }
        if (blockIdx.x == 0 && blockIdx.y == 0) {
            int hh = tid >> 5, cc = tid & 31;
            sg.Ch[(size_t)hh * HSZ_H + cc] = __float2half(0.f);
            sg.Ch[(size_t)hh * HSZ_H + (size_t)16321 * 32 + cc] = __float2half(0.f);
        }
    } else {
        #pragma unroll
        for (int mi = 0; mi < 2; ++mi) {
            int row0 = bm + wm * 32 + mi * 16 + g;
            #pragma unroll
            for (int ni = 0; ni < 4; ++ni) {
                int lcol = wn * 32 + ni * 8 + t * 2;
                float2 bv2 = *(const float2*)(sg.bias + sg.boff + lcol);
                float v00 = acc[mi][ni][0] + bv2.x, v01 = acc[mi][ni][1] + bv2.y;
                float v10 = acc[mi][ni][2] + bv2.x, v11 = acc[mi][ni][3] + bv2.y;
                *(float2*)(sg.Cf + (size_t)row0 * sg.ldc + sg.cn0 + lcol)       = make_float2(v00, v01);
                *(float2*)(sg.Cf + (size_t)(row0 + 8) * sg.ldc + sg.cn0 + lcol) = make_float2(v10, v11);
            }
        }
    }
}

// ---------------- Deformable sampling + softmax v6 ----------------
// Pre-packed broadcast half2 weights in smem: per-iter = 2x LDS.64 + 2 LDG
// + 8 HFMA2 (no SEL/F2FP in the hot loop).
__global__ __launch_bounds__(256) void deform_kernel(
    const float* __restrict__ proj,
    const __half* __restrict__ value,
    const float* __restrict__ refp,
    const float* __restrict__ toff,
    __half* __restrict__ mid)
{
    __shared__ uint4 smw[256];   // per point: {(wx,wx),(wz,wz),(wy,wy),(ww,ww)}
    __shared__ int2  smb[256];

    const int q    = blockIdx.x;
    const int warp = threadIdx.x >> 5;
    const int lane = threadIdx.x & 31;
    const int h = warp;
    const int l = lane >> 3;
    const int p = lane & 7;

    const int   Wv = 64 >> l;
    const int   TH = 192 >> l;
    const int   start = 16384 - (16384 >> (2 * l));
    const float invW  = __uint_as_float((uint32_t)(121 + l) << 23);
    const float invTH = invW * 0.3333333333333333f;

    const float* prow = proj + (size_t)q * PROJN;

    int logit_col = (p < 4) ? (512 + h * 16 + l * 4 + p)
                            : (640 + h * 16 + l * 4 + (p - 4));
    float logit = prow[logit_col];
    float mx = logit;
    #pragma unroll
    for (int off = 16; off; off >>= 1) mx = fmaxf(mx, __shfl_xor_sync(0xffffffffu, mx, off));
    float e = __expf(logit - mx);
    float s = e;
    #pragma unroll
    for (int off = 16; off; off >>= 1) s += __shfl_xor_sync(0xffffffffu, s, off);
    float attnw = e / s;

    float rx = refp[q * 8 + l * 2 + 0];
    float ry = refp[q * 8 + l * 2 + 1];
    float ox, oy;
    if (p < 4) {
        int col = ((h * 4 + l) * 4 + p) * 2;
        ox = prow[col + 0] * invW;
        oy = prow[col + 1] * invTH;
    } else {
        int tw = (p - 4) >> 1, tp = (p - 4) & 1;
        int col = 256 + (((h * 4 + l) * 2 + tw) * 2 + tp) * 2;
        int tob = ((q * 4 + l) * 2 + tw) * 2;
        ox = toff[tob + 0] + prow[col + 0] * invW;
        oy = toff[tob + 1] + prow[col + 1] * invTH;
    }
    float x = (rx + ox) * (float)Wv - 0.5f;
    float y = (ry + oy) * (float)TH - 0.5f;

    float x0f = floorf(x), y0f = floorf(y);
    float lx = x - x0f, ly = y - y0f;
    int x0 = (int)x0f, y0 = (int)y0f;
    int x1 = x0 + 1,   y1 = y0 + 1;

    bool ix0 = (x0 >= 0) & (x0 < Wv);
    bool ix1 = (x1 >= 0) & (x1 < Wv);
    bool iy0 = (y0 >= 0) & (y0 < TH);
    bool iy1 = (y1 >= 0) & (y1 < TH);
    int cy0 = min(max(y0, 0), TH - 1);
    int cy1 = min(max(y1, 0), TH - 1);

    float wx = attnw * (1.f - lx) * (1.f - ly) * (float)(ix0 & iy0);
    float wy = attnw * lx         * (1.f - ly) * (float)(ix1 & iy0);
    float wz = attnw * (1.f - lx) * ly         * (float)(ix0 & iy1);
    float ww = attnw * lx         * ly         * (float)(ix1 & iy1);

    int xb   = min(max(x0, -1), Wv - 1);
    int odd  = xb & 1;
    int shift = 1 + (odd ^ 1);
    int cbase = (odd ? 0 : VHALF) + h * HSZ_H;
    int pix0 = start + cy0 * Wv + xb;
    int pix1 = start + cy1 * Wv + xb;
    int2 bb;
    bb.x = cbase + (pix0 + shift) * 32;
    bb.y = cbase + (pix1 + shift) * 32;

    // pack broadcast half2 weights: uint2 view index (point*2 + xs)
    {
        uint4 wp;
        __half2 hx = __float2half2_rn(wx);
        __half2 hz = __float2half2_rn(wz);
        __half2 hy = __float2half2_rn(wy);
        __half2 hw2 = __float2half2_rn(ww);
        wp.x = *(uint32_t*)&hx;   // xs=0: w0h (y0 row, x0)
        wp.y = *(uint32_t*)&hz;   // xs=0: w1h (y1 row, x0)
        wp.z = *(uint32_t*)&hy;   // xs=1: w0h (y0 row, x1)
        wp.w = *(uint32_t*)&hw2;  // xs=1: w1h (y1 row, x1)
        smw[threadIdx.x] = wp;
    }
    smb[threadIdx.x] = bb;
    __syncwarp();

    const int gg = lane >> 3;
    const int u  = lane & 7;
    const int xs = u >> 2;
    const int uoff = u << 3;
    const int sbase = (warp << 5) + (gg << 3);
    const uint2* wv2 = (const uint2*)smw;

    float accf[8] = {};
    #pragma unroll
    for (int seg = 0; seg < 2; ++seg) {
        __half2 acch[4];
        #pragma unroll
        for (int j = 0; j < 4; ++j) acch[j] = __half2half2(__float2half(0.f));
        #pragma unroll
        for (int pi4 = 0; pi4 < 4; ++pi4) {
            int pi = seg * 4 + pi4;
            uint2 wh = wv2[((sbase + pi) << 1) + xs];
            __half2 w0h = *(__half2*)&wh.x;
            __half2 w1h = *(__half2*)&wh.y;
            int2  bp = smb[sbase + pi];
            uint4 v0 = __ldcg((const uint4*)(value + bp.x + uoff));
            uint4 v1 = __ldcg((const uint4*)(value + bp.y + uoff));
            const __half2* p0 = (const __half2*)&v0;
            const __half2* p1 = (const __half2*)&v1;
            #pragma unroll
            for (int j = 0; j < 4; ++j) {
                acch[j] = __hfma2(p0[j], w0h, acch[j]);
                acch[j] = __hfma2(p1[j], w1h, acch[j]);
            }
        }
        #pragma unroll
        for (int j = 0; j < 4; ++j) {
            float2 f = __half22float2(acch[j]);
            accf[2 * j]     += f.x;
            accf[2 * j + 1] += f.y;
        }
    }
    #pragma unroll
    for (int j = 0; j < 8; ++j) {
        accf[j] += __shfl_xor_sync(0xffffffffu, accf[j], 4);
        accf[j] += __shfl_xor_sync(0xffffffffu, accf[j], 8);
        accf[j] += __shfl_xor_sync(0xffffffffu, accf[j], 16);
    }
    if (lane < 4) {
        uint4 o8;
        o8.x = pack2(accf[0], accf[1]);
        o8.y = pack2(accf[2], accf[3]);
        o8.z = pack2(accf[4], accf[5]);
        o8.w = pack2(accf[6], accf[7]);
        *(uint4*)(mid + (size_t)q * DIM + warp * DHEAD + (lane << 3)) = o8;
    }
}

// ---------------- launch ----------------
extern "C" void kernel_launch(void* const* d_in, const int* in_sizes, int n_in,
                              void* d_out, int out_size)
{
    const float* query = (const float*)d_in[0];
    const float* refp  = (const float*)d_in[1];
    const float* toff  = (const float*)d_in[2];
    const float* inpf  = (const float*)d_in[3];
    const float* W_so  = (const float*)d_in[6];
    const float* b_so  = (const float*)d_in[7];
    const float* W_tso = (const float*)d_in[8];
    const float* b_tso = (const float*)d_in[9];
    const float* W_aw  = (const float*)d_in[10];
    const float* b_aw  = (const float*)d_in[11];
    const float* W_taw = (const float*)d_in[12];
    const float* b_taw = (const float*)d_in[13];
    const float* W_v   = (const float*)d_in[14];
    const float* b_v   = (const float*)d_in[15];
    const float* W_o   = (const float*)d_in[16];
    const float* b_o   = (const float*)d_in[17];
    float* out = (float*)d_out;

    __half *value, *mid, *hq, *hi, *hw; float *proj;
    cudaGetSymbolAddress((void**)&value, g_value);
    cudaGetSymbolAddress((void**)&proj,  g_proj);
    cudaGetSymbolAddress((void**)&mid,   g_mid);
    cudaGetSymbolAddress((void**)&hq,    g_hq);
    cudaGetSymbolAddress((void**)&hi,    g_hi);
    cudaGetSymbolAddress((void**)&hw,    g_hw);

    dim3 blk(256);

    // (1) fp32 -> fp16 prep
    {
        int nthr = (2 * NQE + WTOT) / 8;
        prep_kernel<<<nthr / 256, 256>>>(query, inpf, W_v, W_so, W_tso, W_aw, W_taw, W_o,
                                         hq, hi, hw);
    }
    // (2) fused value + projections GEMM (8 segments, 64-row tiles)
    {
        SegArr sa{};
        for (int i = 0; i < 2; ++i) {
            sa.s[i].A = hi; sa.s[i].B = hw + WV_OFF; sa.s[i].bias = b_v;
            sa.s[i].Ch = value; sa.s[i].ldb = 256; sa.s[i].boff = i * 128;
            sa.s[i].ldc = DIM; sa.s[i].cn0 = i * 128; sa.s[i].ishalf = 1;
        }
        for (int i = 0; i < 2; ++i) {
            sa.s[2 + i].A = hq; sa.s[2 + i].B = hw + WSO_OFF; sa.s[2 + i].bias = b_so;
            sa.s[2 + i].Cf = proj; sa.s[2 + i].ldb = 256; sa.s[2 + i].boff = i * 128;
            sa.s[2 + i].ldc = PROJN; sa.s[2 + i].cn0 = i * 128; sa.s[2 + i].ishalf = 0;
            sa.s[4 + i].A = hq; sa.s[4 + i].B = hw + WTSO_OFF; sa.s[4 + i].bias = b_tso;
            sa.s[4 + i].Cf = proj; sa.s[4 + i].ldb = 256; sa.s[4 + i].boff = i * 128;
            sa.s[4 + i].ldc = PROJN; sa.s[4 + i].cn0 = 256 + i * 128; sa.s[4 + i].ishalf = 0;
        }
        sa.s[6].A = hq; sa.s[6].B = hw + WAW_OFF; sa.s[6].bias = b_aw;
        sa.s[6].Cf = proj; sa.s[6].ldb = 128; sa.s[6].boff = 0;
        sa.s[6].ldc = PROJN; sa.s[6].cn0 = 512; sa.s[6].ishalf = 0;
        sa.s[7].A = hq; sa.s[7].B = hw + WTAW_OFF; sa.s[7].bias = b_taw;
        sa.s[7].Cf = proj; sa.s[7].ldb = 128; sa.s[7].boff = 0;
        sa.s[7].ldc = PROJN; sa.s[7].cn0 = 640; sa.s[7].ishalf = 0;
        mma_gemm_v6<<<dim3(8, LQ / 64), blk>>>(sa);
    }
    // (3) deform
    deform_kernel<<<LQ, 256>>>(proj, value, refp, toff, mid);
    // (4) out = mid @ W_o + b_o (64-row tiles)
    {
        SegArr sa{};
        for (int i = 0; i < 2; ++i) {
            sa.s[i].A = mid; sa.s[i].B = hw + WO_OFF; sa.s[i].bias = b_o;
            sa.s[i].Cf = out; sa.s[i].ldb = 256; sa.s[i].boff = i * 128;
            sa.s[i].ldc = DIM; sa.s[i].cn0 = i * 128; sa.s[i].ishalf = 0;
        }
        mma_gemm_v6<<<dim3(2, LQ / 64), blk>>>(sa);
    }
}

// round 17
// speedup vs baseline: 1.1680x; 1.0092x over previous
#include <cuda_runtime.h>
#include <cuda_fp16.h>
#include <math.h>
#include <stdint.h>

// Problem constants (fixed by setup_inputs)
#define DIM   256
#define NHEAD 8
#define DHEAD 32
#define LQ    16320
#define PROJN 768
#define NQE   (LQ * DIM)

// Head-major value, two alignment copies (see deform v4).
#define HSZ_H (16324 * 32)
#define VHALF (8 * HSZ_H)

// fp16 weight buffer offsets (halfs)
#define WV_OFF   0
#define WSO_OFF  65536
#define WTSO_OFF 131072
#define WAW_OFF  196608
#define WTAW_OFF 229376
#define WO_OFF   262144
#define WTOT     327680

// Scratch (device globals)
__device__ __half g_value[16 * HSZ_H];
__device__ float  g_proj [LQ * PROJN];
__device__ __half g_mid  [LQ * DIM];
__device__ __half g_hq   [NQE];
__device__ __half g_hi   [NQE];
__device__ __half g_hw   [WTOT];

// ---------------- prep: fp32 -> fp16 one-pass convert ----------------
__device__ __forceinline__ uint32_t pack2(float a, float b) {
    __half2 h = __floats2half2_rn(a, b);
    return *(uint32_t*)&h;
}
__device__ __forceinline__ uint4 pack8(float4 v0, float4 v1) {
    uint4 u;
    u.x = pack2(v0.x, v0.y); u.y = pack2(v0.z, v0.w);
    u.z = pack2(v1.x, v1.y); u.w = pack2(v1.z, v1.w);
    return u;
}
__device__ __forceinline__ void cvt8(const float* s, __half* d) {
    float4 v0 = *(const float4*)(s);
    float4 v1 = *(const float4*)(s + 4);
    *(uint4*)d = pack8(v0, v1);
}

__global__ __launch_bounds__(256) void prep_kernel(
    const float* __restrict__ q, const float* __restrict__ inp,
    const float* __restrict__ wv, const float* __restrict__ wso,
    const float* __restrict__ wtso, const float* __restrict__ waw,
    const float* __restrict__ wtaw, const float* __restrict__ wo,
    __half* __restrict__ hq, __half* __restrict__ hi, __half* __restrict__ hw)
{
    int base = (blockIdx.x * 256 + threadIdx.x) * 8;
    if (base < NQE) {
        cvt8(q + base, hq + base);
    } else if (base < 2 * NQE) {
        int b = base - NQE;
        cvt8(inp + b, hi + b);
    } else {
        int b = base - 2 * NQE;
        if (b < WTOT) {
            const float* src; int off;
            if      (b < WSO_OFF)  { src = wv;   off = b; }
            else if (b < WTSO_OFF) { src = wso;  off = b - WSO_OFF; }
            else if (b < WAW_OFF)  { src = wtso; off = b - WTSO_OFF; }
            else if (b < WTAW_OFF) { src = waw;  off = b - WAW_OFF; }
            else if (b < WO_OFF)   { src = wtaw; off = b - WTAW_OFF; }
            else                   { src = wo;   off = b - WO_OFF; }
            cvt8(src + off, hw + b);
        }
    }
}

// Zero the value pads (copy A slots 0 and 16321..16323; copy B slots 0,1 and
// 16322,16323). 512 threads is plenty; also shifts deform to launch #4.
__global__ void zpad_kernel(__half* v)
{
    int hh = threadIdx.x >> 5, cc = threadIdx.x & 31;
    // copy A: pixel p at slot p+1 -> pads at slot 0 and slots 16321..16323
    __half z = __float2half(0.f);
    size_t a = (size_t)hh * HSZ_H;
    v[a + cc] = z;
    v[a + (size_t)16321 * 32 + cc] = z;
    v[a + (size_t)16322 * 32 + cc] = z;
    v[a + (size_t)16323 * 32 + cc] = z;
    // copy B: pixel p at slot p+2 -> pads at slots 0,1 and 16322,16323
    size_t b = (size_t)VHALF + (size_t)hh * HSZ_H;
    v[b + cc] = z;
    v[b + 32 + cc] = z;
    v[b + (size_t)16322 * 32 + cc] = z;
    v[b + (size_t)16323 * 32 + cc] = z;
}

// ---------------- FP16 GEMM v7: cp.async 3-stage, eager LDSM --------------
#define GBN 128
#define AROW 40
#define BROW 136
#define BBUFB (32 * BROW * 2)
#define ABUFB (64 * AROW * 2)

struct Seg {
    const __half* A;
    const __half* B;
    const float*  bias;
    float*  Cf;
    __half* Ch;
    int ldb, boff, ldc, cn0, ishalf;
};
struct SegArr { Seg s[8]; };

__device__ __forceinline__ void cp16(uint32_t dst, const void* src) {
    asm volatile("cp.async.cg.shared.global [%0], [%1], 16;" :: "r"(dst), "l"(src));
}
__device__ __forceinline__ void ldsm4(uint32_t* r, uint32_t addr) {
    asm volatile("ldmatrix.sync.aligned.m8n8.x4.shared.b16 {%0,%1,%2,%3}, [%4];"
        : "=r"(r[0]), "=r"(r[1]), "=r"(r[2]), "=r"(r[3]) : "r"(addr));
}
__device__ __forceinline__ void ldsm4t(uint32_t* r, uint32_t addr) {
    asm volatile("ldmatrix.sync.aligned.m8n8.x4.trans.shared.b16 {%0,%1,%2,%3}, [%4];"
        : "=r"(r[0]), "=r"(r[1]), "=r"(r[2]), "=r"(r[3]) : "r"(addr));
}

__global__ __launch_bounds__(256) void mma_gemm_v7(SegArr sa)
{
    __shared__ __half As[3 * 64 * AROW];
    __shared__ __half Bs[3 * 32 * BROW];

    const Seg sg = sa.s[blockIdx.x];
    const int tid = threadIdx.x;
    const int bm  = blockIdx.y * 64;

    const int lane = tid & 31, wid = tid >> 5;
    const int wm = wid >> 2, wn = wid & 3;
    const int g = lane >> 2, t = lane & 3;

    const int arow_f = tid >> 2;
    const int acol_f = (tid & 3) << 3;
    const __half* Agp = sg.A + (size_t)(bm + arow_f) * 256 + acol_f;
    const uint32_t as0 = (uint32_t)__cvta_generic_to_shared(As) +
                         ((arow_f * AROW + acol_f) << 1);

    const __half* Bgp0 = sg.B + (size_t)(tid >> 4) * sg.ldb + sg.boff + ((tid & 15) << 3);
    const __half* Bgp1 = Bgp0 + (size_t)16 * sg.ldb;
    const uint32_t bs0 = (uint32_t)__cvta_generic_to_shared(Bs) +
                         ((((tid >> 4) * BROW) + ((tid & 15) << 3)) << 1);
    const uint32_t bs1 = bs0 + 16 * BROW * 2;

    const uint32_t as_base = (uint32_t)__cvta_generic_to_shared(As);
    const uint32_t bs_base = (uint32_t)__cvta_generic_to_shared(Bs);
    const int arow = wm * 32 + (lane & 7) + ((lane >> 3) & 1) * 8;
    const int acol = (lane >> 4) * 8;
    const int brow = (lane & 7) + ((lane >> 3) & 1) * 8;
    const int bcol = wn * 32 + (lane >> 4) * 8;
    const uint32_t aaddr0 = as_base + (uint32_t)((arow * AROW + acol) * 2);
    const uint32_t baddr0 = bs_base + (uint32_t)((brow * BROW + bcol) * 2);

    float acc[2][4][4] = {};

    #pragma unroll
    for (int s = 0; s < 2; ++s) {
        const int k0 = s * 32;
        cp16(as0 + s * ABUFB, Agp + k0);
        cp16(bs0 + s * BBUFB, Bgp0 + (size_t)k0 * sg.ldb);
        cp16(bs1 + s * BBUFB, Bgp1 + (size_t)k0 * sg.ldb);
        asm volatile("cp.async.commit_group;");
    }

    #pragma unroll
    for (int s = 0; s < 8; ++s) {
        if (s < 7) asm volatile("cp.async.wait_group 1;");
        else       asm volatile("cp.async.wait_group 0;");
        __syncthreads();

        if (s + 2 < 8) {
            const int st = (s + 2) % 3;
            const int k0 = (s + 2) * 32;
            cp16(as0 + st * ABUFB, Agp + k0);
            cp16(bs0 + st * BBUFB, Bgp0 + (size_t)k0 * sg.ldb);
            cp16(bs1 + st * BBUFB, Bgp1 + (size_t)k0 * sg.ldb);
            asm volatile("cp.async.commit_group;");
        }

        const int cur = s % 3;
        const uint32_t ab = aaddr0 + (uint32_t)(cur * ABUFB);
        const uint32_t bb = baddr0 + (uint32_t)(cur * BBUFB);

        // eager: load ALL fragments for both k16 steps, then do 32 MMAs
        uint32_t a[2][2][4], b[2][2][4];
        #pragma unroll
        for (int ks = 0; ks < 2; ++ks) {
            #pragma unroll
            for (int mi = 0; mi < 2; ++mi)
                ldsm4(a[ks][mi], ab + (uint32_t)((mi * 16 * AROW + ks * 16) * 2));
            #pragma unroll
            for (int nip = 0; nip < 2; ++nip)
                ldsm4t(b[ks][nip], bb + (uint32_t)((ks * 16 * BROW + nip * 16) * 2));
        }
        #pragma unroll
        for (int ks = 0; ks < 2; ++ks)
            #pragma unroll
            for (int mi = 0; mi < 2; ++mi)
                #pragma unroll
                for (int ni = 0; ni < 4; ++ni) {
                    uint32_t b0 = b[ks][ni >> 1][(ni & 1) * 2];
                    uint32_t b1 = b[ks][ni >> 1][(ni & 1) * 2 + 1];
                    asm volatile(
                        "mma.sync.aligned.m16n8k16.row.col.f32.f16.f16.f32 "
                        "{%0,%1,%2,%3}, {%4,%5,%6,%7}, {%8,%9}, {%0,%1,%2,%3};"
                        : "+f"(acc[mi][ni][0]), "+f"(acc[mi][ni][1]),
                          "+f"(acc[mi][ni][2]), "+f"(acc[mi][ni][3])
                        : "r"(a[ks][mi][0]), "r"(a[ks][mi][1]),
                          "r"(a[ks][mi][2]), "r"(a[ks][mi][3]),
                          "r"(b0), "r"(b1));
                }
        if (s < 7) __syncthreads();
    }

    // ---- epilogue ----
    if (sg.ishalf) {
        const int head = (sg.cn0 >> 5) + wn;
        __half* baseA = sg.Ch + (size_t)head * HSZ_H;
        __half* baseB = sg.Ch + (size_t)VHALF + (size_t)head * HSZ_H;
        #pragma unroll
        for (int mi = 0; mi < 2; ++mi) {
            int row0 = bm + wm * 32 + mi * 16 + g;
            #pragma unroll
            for (int ni = 0; ni < 4; ++ni) {
                int ch = ni * 8 + t * 2;
                __half2 h0 = __floats2half2_rn(acc[mi][ni][0], acc[mi][ni][1]);
                __half2 h1 = __floats2half2_rn(acc[mi][ni][2], acc[mi][ni][3]);
                *(__half2*)(baseA + (size_t)(row0 + 1) * 32 + ch)  = h0;
                *(__half2*)(baseA + (size_t)(row0 + 9) * 32 + ch)  = h1;
                *(__half2*)(baseB + (size_t)(row0 + 2) * 32 + ch)  = h0;
                *(__half2*)(baseB + (size_t)(row0 + 10) * 32 + ch) = h1;
            }
        }
    } else {
        #pragma unroll
        for (int mi = 0; mi < 2; ++mi) {
            int row0 = bm + wm * 32 + mi * 16 + g;
            #pragma unroll
            for (int ni = 0; ni < 4; ++ni) {
                int lcol = wn * 32 + ni * 8 + t * 2;
                float2 bv2 = *(const float2*)(sg.bias + sg.boff + lcol);
                float v00 = acc[mi][ni][0] + bv2.x, v01 = acc[mi][ni][1] + bv2.y;
                float v10 = acc[mi][ni][2] + bv2.x, v11 = acc[mi][ni][3] + bv2.y;
                *(float2*)(sg.Cf + (size_t)row0 * sg.ldc + sg.cn0 + lcol)       = make_float2(v00, v01);
                *(float2*)(sg.Cf + (size_t)(row0 + 8) * sg.ldc + sg.cn0 + lcol) = make_float2(v10, v11);
            }
        }
    }
}

// ---------------- Deformable sampling + softmax v6 (unchanged) ------------
__global__ __launch_bounds__(256) void deform_kernel(
    const float* __restrict__ proj,
    const __half* __restrict__ value,
    const float* __restrict__ refp,
    const float* __restrict__ toff,
    __half* __restrict__ mid)
{
    __shared__ uint4 smw[256];
    __shared__ int2  smb[256];

    const int q    = blockIdx.x;
    const int warp = threadIdx.x >> 5;
    const int lane = threadIdx.x & 31;
    const int h = warp;
    const int l = lane >> 3;
    const int p = lane & 7;

    const int   Wv = 64 >> l;
    const int   TH = 192 >> l;
    const int   start = 16384 - (16384 >> (2 * l));
    const float invW  = __uint_as_float((uint32_t)(121 + l) << 23);
    const float invTH = invW * 0.3333333333333333f;

    const float* prow = proj + (size_t)q * PROJN;

    int logit_col = (p < 4) ? (512 + h * 16 + l * 4 + p)
                            : (640 + h * 16 + l * 4 + (p - 4));
    float logit = prow[logit_col];
    float mx = logit;
    #pragma unroll
    for (int off = 16; off; off >>= 1) mx = fmaxf(mx, __shfl_xor_sync(0xffffffffu, mx, off));
    float e = __expf(logit - mx);
    float s = e;
    #pragma unroll
    for (int off = 16; off; off >>= 1) s += __shfl_xor_sync(0xffffffffu, s, off);
    float attnw = e / s;

    float rx = refp[q * 8 + l * 2 + 0];
    float ry = refp[q * 8 + l * 2 + 1];
    float ox, oy;
    if (p < 4) {
        int col = ((h * 4 + l) * 4 + p) * 2;
        ox = prow[col + 0] * invW;
        oy = prow[col + 1] * invTH;
    } else {
        int tw = (p - 4) >> 1, tp = (p - 4) & 1;
        int col = 256 + (((h * 4 + l) * 2 + tw) * 2 + tp) * 2;
        int tob = ((q * 4 + l) * 2 + tw) * 2;
        ox = toff[tob + 0] + prow[col + 0] * invW;
        oy = toff[tob + 1] + prow[col + 1] * invTH;
    }
    float x = (rx + ox) * (float)Wv - 0.5f;
    float y = (ry + oy) * (float)TH - 0.5f;

    float x0f = floorf(x), y0f = floorf(y);
    float lx = x - x0f, ly = y - y0f;
    int x0 = (int)x0f, y0 = (int)y0f;
    int x1 = x0 + 1,   y1 = y0 + 1;

    bool ix0 = (x0 >= 0) & (x0 < Wv);
    bool ix1 = (x1 >= 0) & (x1 < Wv);
    bool iy0 = (y0 >= 0) & (y0 < TH);
    bool iy1 = (y1 >= 0) & (y1 < TH);
    int cy0 = min(max(y0, 0), TH - 1);
    int cy1 = min(max(y1, 0), TH - 1);

    float wx = attnw * (1.f - lx) * (1.f - ly) * (float)(ix0 & iy0);
    float wy = attnw * lx         * (1.f - ly) * (float)(ix1 & iy0);
    float wz = attnw * (1.f - lx) * ly         * (float)(ix0 & iy1);
    float ww = attnw * lx         * ly         * (float)(ix1 & iy1);

    int xb   = min(max(x0, -1), Wv - 1);
    int odd  = xb & 1;
    int shift = 1 + (odd ^ 1);
    int cbase = (odd ? 0 : VHALF) + h * HSZ_H;
    int pix0 = start + cy0 * Wv + xb;
    int pix1 = start + cy1 * Wv + xb;
    int2 bb;
    bb.x = cbase + (pix0 + shift) * 32;
    bb.y = cbase + (pix1 + shift) * 32;

    {
        uint4 wp;
        __half2 hx = __float2half2_rn(wx);
        __half2 hz = __float2half2_rn(wz);
        __half2 hy = __float2half2_rn(wy);
        __half2 hw2 = __float2half2_rn(ww);
        wp.x = *(uint32_t*)&hx;
        wp.y = *(uint32_t*)&hz;
        wp.z = *(uint32_t*)&hy;
        wp.w = *(uint32_t*)&hw2;
        smw[threadIdx.x] = wp;
    }
    smb[threadIdx.x] = bb;
    __syncwarp();

    const int gg = lane >> 3;
    const int u  = lane & 7;
    const int xs = u >> 2;
    const int uoff = u << 3;
    const int sbase = (warp << 5) + (gg << 3);
    const uint2* wv2 = (const uint2*)smw;

    float accf[8] = {};
    #pragma unroll
    for (int seg = 0; seg < 2; ++seg) {
        __half2 acch[4];
        #pragma unroll
        for (int j = 0; j < 4; ++j) acch[j] = __half2half2(__float2half(0.f));
        #pragma unroll
        for (int pi4 = 0; pi4 < 4; ++pi4) {
            int pi = seg * 4 + pi4;
            uint2 wh = wv2[((sbase + pi) << 1) + xs];
            __half2 w0h = *(__half2*)&wh.x;
            __half2 w1h = *(__half2*)&wh.y;
            int2  bp = smb[sbase + pi];
            uint4 v0 = __ldcg((const uint4*)(value + bp.x + uoff));
            uint4 v1 = __ldcg((const uint4*)(value + bp.y + uoff));
            const __half2* p0 = (const __half2*)&v0;
            const __half2* p1 = (const __half2*)&v1;
            #pragma unroll
            for (int j = 0; j < 4; ++j) {
                acch[j] = __hfma2(p0[j], w0h, acch[j]);
                acch[j] = __hfma2(p1[j], w1h, acch[j]);
            }
        }
        #pragma unroll
        for (int j = 0; j < 4; ++j) {
            float2 f = __half22float2(acch[j]);
            accf[2 * j]     += f.x;
            accf[2 * j + 1] += f.y;
        }
    }
    #pragma unroll
    for (int j = 0; j < 8; ++j) {
        accf[j] += __shfl_xor_sync(0xffffffffu, accf[j], 4);
        accf[j] += __shfl_xor_sync(0xffffffffu, accf[j], 8);
        accf[j] += __shfl_xor_sync(0xffffffffu, accf[j], 16);
    }
    if (lane < 4) {
        uint4 o8;
        o8.x = pack2(accf[0], accf[1]);
        o8.y = pack2(accf[2], accf[3]);
        o8.z = pack2(accf[4], accf[5]);
        o8.w = pack2(accf[6], accf[7]);
        *(uint4*)(mid + (size_t)q * DIM + warp * DHEAD + (lane << 3)) = o8;
    }
}

// ---------------- launch ----------------
extern "C" void kernel_launch(void* const* d_in, const int* in_sizes, int n_in,
                              void* d_out, int out_size)
{
    const float* query = (const float*)d_in[0];
    const float* refp  = (const float*)d_in[1];
    const float* toff  = (const float*)d_in[2];
    const float* inpf  = (const float*)d_in[3];
    const float* W_so  = (const float*)d_in[6];
    const float* b_so  = (const float*)d_in[7];
    const float* W_tso = (const float*)d_in[8];
    const float* b_tso = (const float*)d_in[9];
    const float* W_aw  = (const float*)d_in[10];
    const float* b_aw  = (const float*)d_in[11];
    const float* W_taw = (const float*)d_in[12];
    const float* b_taw = (const float*)d_in[13];
    const float* W_v   = (const float*)d_in[14];
    const float* b_v   = (const float*)d_in[15];
    const float* W_o   = (const float*)d_in[16];
    const float* b_o   = (const float*)d_in[17];
    float* out = (float*)d_out;

    __half *value, *mid, *hq, *hi, *hw; float *proj;
    cudaGetSymbolAddress((void**)&value, g_value);
    cudaGetSymbolAddress((void**)&proj,  g_proj);
    cudaGetSymbolAddress((void**)&mid,   g_mid);
    cudaGetSymbolAddress((void**)&hq,    g_hq);
    cudaGetSymbolAddress((void**)&hi,    g_hi);
    cudaGetSymbolAddress((void**)&hw,    g_hw);

    dim3 blk(256);

    // (1) fp32 -> fp16 prep
    {
        int nthr = (2 * NQE + WTOT) / 8;
        prep_kernel<<<nthr / 256, 256>>>(query, inpf, W_v, W_so, W_tso, W_aw, W_taw, W_o,
                                         hq, hi, hw);
    }
    // (2) fused value + projections GEMM (8 segments, 64-row tiles)
    {
        SegArr sa{};
        for (int i = 0; i < 2; ++i) {
            sa.s[i].A = hi; sa.s[i].B = hw + WV_OFF; sa.s[i].bias = b_v;
            sa.s[i].Ch = value; sa.s[i].ldb = 256; sa.s[i].boff = i * 128;
            sa.s[i].ldc = DIM; sa.s[i].cn0 = i * 128; sa.s[i].ishalf = 1;
        }
        for (int i = 0; i < 2; ++i) {
            sa.s[2 + i].A = hq; sa.s[2 + i].B = hw + WSO_OFF; sa.s[2 + i].bias = b_so;
            sa.s[2 + i].Cf = proj; sa.s[2 + i].ldb = 256; sa.s[2 + i].boff = i * 128;
            sa.s[2 + i].ldc = PROJN; sa.s[2 + i].cn0 = i * 128; sa.s[2 + i].ishalf = 0;
            sa.s[4 + i].A = hq; sa.s[4 + i].B = hw + WTSO_OFF; sa.s[4 + i].bias = b_tso;
            sa.s[4 + i].Cf = proj; sa.s[4 + i].ldb = 256; sa.s[4 + i].boff = i * 128;
            sa.s[4 + i].ldc = PROJN; sa.s[4 + i].cn0 = 256 + i * 128; sa.s[4 + i].ishalf = 0;
        }
        sa.s[6].A = hq; sa.s[6].B = hw + WAW_OFF; sa.s[6].bias = b_aw;
        sa.s[6].Cf = proj; sa.s[6].ldb = 128; sa.s[6].boff = 0;
        sa.s[6].ldc = PROJN; sa.s[6].cn0 = 512; sa.s[6].ishalf = 0;
        sa.s[7].A = hq; sa.s[7].B = hw + WTAW_OFF; sa.s[7].bias = b_taw;
        sa.s[7].Cf = proj; sa.s[7].ldb = 128; sa.s[7].boff = 0;
        sa.s[7].ldc = PROJN; sa.s[7].cn0 = 640; sa.s[7].ishalf = 0;
        mma_gemm_v7<<<dim3(8, LQ / 64), blk>>>(sa);
    }
    // (3) zero value pads (also aligns deform to ncu's captured launch #4)
    zpad_kernel<<<1, 256>>>(value);
    // (4) deform
    deform_kernel<<<LQ, 256>>>(proj, value, refp, toff, mid);
    // (5) out = mid @ W_o + b_o (64-row tiles)
    {
        SegArr sa{};
        for (int i = 0; i < 2; ++i) {
            sa.s[i].A = mid; sa.s[i].B = hw + WO_OFF; sa.s[i].bias = b_o;
            sa.s[i].Cf = out; sa.s[i].ldb = 256; sa.s[i].boff = i * 128;
            sa.s[i].ldc = DIM; sa.s[i].cn0 = i * 128; sa.s[i].ishalf = 0;
        }
        mma_gemm_v7<<<dim3(2, LQ / 64), blk>>>(sa);
    }
}